// round 15
// baseline (speedup 1.0000x reference)
#include <cuda_runtime.h>
#include <cuda_fp16.h>
#include <cstdint>

// Problem constants: S=16, P=8, N=64, D=128
#define NBLK   128
#define NROW   64
#define DIMD   128
#define QH     68      // half2 row stride (68 mod 32 == 4 -> conflict-free LDS.128)
#define NTHR   1024

// smem: qx[64][68](u32/half2), qy[64][68], nx2/rnx/ny2/rny/sxs/sys[64]
#define SMEM_BYTES (2 * NROW * QH * 4 + 6 * NROW * 4)

__device__ __forceinline__ __half2 asH2(uint32_t u) {
    __half2 h;
    *(uint32_t*)&h = u;
    return h;
}

// One pipelined stage: 4 pairs x 4 half2 k-words; tree adds into [2]-split accums.
// Per pair: 4 HMNMX2 + 2 tree HADD2 + 2 acc HADD2 = 8 ops (1 slot / element).
#define STEP(X0, X1, Y0, Y1)                                                   \
    do {                                                                       \
        _Pragma("unroll")                                                      \
        for (int i = 0; i < 2; i++) {                                          \
            const uint4 xx = (i == 0) ? (X0) : (X1);                           \
            _Pragma("unroll")                                                  \
            for (int j = 0; j < 2; j++) {                                      \
                const uint4 yy = (j == 0) ? (Y0) : (Y1);                       \
                __half2 m0 = __hmax2(asH2(xx.x), asH2(yy.x));                  \
                __half2 m1 = __hmax2(asH2(xx.y), asH2(yy.y));                  \
                __half2 m2 = __hmax2(asH2(xx.z), asH2(yy.z));                  \
                __half2 m3 = __hmax2(asH2(xx.w), asH2(yy.w));                  \
                acc[i][j][0] = __hadd2(acc[i][j][0], __hadd2(m0, m1));         \
                acc[i][j][1] = __hadd2(acc[i][j][1], __hadd2(m2, m3));         \
            }                                                                  \
        }                                                                      \
    } while (0)

__global__ void __launch_bounds__(NTHR, 1)
vcmp_kernel(const float* __restrict__ X, const float* __restrict__ Y,
            float* __restrict__ out) {
    extern __shared__ uint32_t smem_u[];
    uint32_t* qx = smem_u;
    uint32_t* qy = qx + NROW * QH;
    float* nx2 = (float*)(qy + NROW * QH);
    float* rnx = nx2 + NROW;
    float* ny2 = rnx + NROW;
    float* rny = ny2 + NROW;
    float* sxs = rny + NROW;
    float* sys = sxs + NROW;

    const int blk = blockIdx.x;
    const int t   = threadIdx.x;
    const int wid = t >> 5;
    const int lid = t & 31;

    // ---- Load + convert + per-row reductions fused (warp wid owns row k*32+wid) ----
    const float4* xg = (const float4*)(X + (size_t)blk * NROW * DIMD);
    const float4* yg = (const float4*)(Y + (size_t)blk * NROW * DIMD);
#pragma unroll
    for (int k = 0; k < 2; k++) {
        const int g    = k * NTHR + t;
        const int row  = k * 32 + wid;
        const int word = (g & 31) * 2;
        float4 xv = xg[g];
        float4 yv = yg[g];

        __half2 hx0 = __float22half2_rn(make_float2(xv.x, xv.y));
        __half2 hx1 = __float22half2_rn(make_float2(xv.z, xv.w));
        __half2 hy0 = __float22half2_rn(make_float2(yv.x, yv.y));
        __half2 hy1 = __float22half2_rn(make_float2(yv.z, yv.w));
        *(uint2*)(qx + row * QH + word) = make_uint2(*(uint32_t*)&hx0, *(uint32_t*)&hx1);
        *(uint2*)(qy + row * QH + word) = make_uint2(*(uint32_t*)&hy0, *(uint32_t*)&hy1);

        float2 fx0 = __half22float2(hx0), fx1 = __half22float2(hx1);
        float2 fy0 = __half22float2(hy0), fy1 = __half22float2(hy1);
        float ssx = fx0.x*fx0.x + fx0.y*fx0.y + fx1.x*fx1.x + fx1.y*fx1.y;
        float sx_ = fx0.x + fx0.y + fx1.x + fx1.y;
        float ssy = fy0.x*fy0.x + fy0.y*fy0.y + fy1.x*fy1.x + fy1.y*fy1.y;
        float sy_ = fy0.x + fy0.y + fy1.x + fy1.y;
#pragma unroll
        for (int off = 16; off > 0; off >>= 1) {
            ssx += __shfl_xor_sync(0xffffffffu, ssx, off);
            sx_ += __shfl_xor_sync(0xffffffffu, sx_, off);
            ssy += __shfl_xor_sync(0xffffffffu, ssy, off);
            sy_ += __shfl_xor_sync(0xffffffffu, sy_, off);
        }
        if (lid == 0) {
            nx2[row] = ssx;
            rnx[row] = 1.0f / fmaxf(sqrtf(ssx), 1e-12f);
            sxs[row] = sx_;
            ny2[row] = ssy;
            rny[row] = 1.0f / fmaxf(sqrtf(ssy), 1e-12f);
            sys[row] = sy_;
        }
    }
    __syncthreads();

    // ---- Gram via mma.sync m16n8k16 f16 (fp32 accum) from half2 smem ----
    const int g_ = lid >> 2;
    const int tg = lid & 3;
    const int n0 = (wid >> 3) * 16;
    const int m0 = (wid & 7) * 8;

    float c0 = 0.f, c1 = 0.f, c2 = 0.f, c3 = 0.f;
    {
        const uint32_t* pa = qx + (n0 + g_) * QH + tg;
        const uint32_t* pb = qy + (m0 + g_) * QH + tg;
#pragma unroll
        for (int kk = 0; kk < 8; kk++) {
            const int w = kk * 8;
            uint32_t a0 = pa[w];
            uint32_t a1 = pa[8 * QH + w];
            uint32_t a2 = pa[w + 4];
            uint32_t a3 = pa[8 * QH + w + 4];
            uint32_t b0 = pb[w];
            uint32_t b1 = pb[w + 4];
            asm volatile(
                "mma.sync.aligned.m16n8k16.row.col.f32.f16.f16.f32 "
                "{%0,%1,%2,%3}, {%4,%5,%6,%7}, {%8,%9}, {%0,%1,%2,%3};"
                : "+f"(c0), "+f"(c1), "+f"(c2), "+f"(c3)
                : "r"(a0), "r"(a1), "r"(a2), "r"(a3), "r"(b0), "r"(b1));
        }
    }

    // ---- L1 loop: fp16 Sum(max), 2-stage ping-pong pipelined LDS.128 ----
    // n = 2*wid + i, m = lid + 32*j; x broadcast, y conflict-free (QH mod 32 == 4)
    const uint32_t* xq0 = qx + (wid * 2) * QH;
    const uint32_t* xq1 = xq0 + QH;
    const uint32_t* yq0 = qy + lid * QH;
    const uint32_t* yq1 = yq0 + 32 * QH;

    __half2 acc[2][2][2];
#pragma unroll
    for (int i = 0; i < 2; i++)
#pragma unroll
        for (int j = 0; j < 2; j++) {
            acc[i][j][0] = __float2half2_rn(0.f);
            acc[i][j][1] = __float2half2_rn(0.f);
        }

    uint4 ax0, ax1, ay0, ay1, bx0, bx1, by0, by1;
    ax0 = *(const uint4*)(xq0);
    ax1 = *(const uint4*)(xq1);
    ay0 = *(const uint4*)(yq0);
    ay1 = *(const uint4*)(yq1);

#pragma unroll
    for (int d2 = 0; d2 < 64; d2 += 8) {   // 8 double-iterations
        bx0 = *(const uint4*)(xq0 + d2 + 4);
        bx1 = *(const uint4*)(xq1 + d2 + 4);
        by0 = *(const uint4*)(yq0 + d2 + 4);
        by1 = *(const uint4*)(yq1 + d2 + 4);
        STEP(ax0, ax1, ay0, ay1);

        // d2=56 prefetch reads words 64..67 (row pad, in-bounds, never used)
        ax0 = *(const uint4*)(xq0 + d2 + 8);
        ax1 = *(const uint4*)(xq1 + d2 + 8);
        ay0 = *(const uint4*)(yq0 + d2 + 8);
        ay1 = *(const uint4*)(yq1 + d2 + 8);
        STEP(bx0, bx1, by0, by1);
    }

    // ---- Stores ----
    float* oblk = out + (size_t)blk * NROW * NROW * 3;

    // L1 = 2*Sum(max) - Sx - Sy
#pragma unroll
    for (int i = 0; i < 2; i++) {
        const int n = wid * 2 + i;
        const float sxn = sxs[n];
#pragma unroll
        for (int j = 0; j < 2; j++) {
            const int m = lid + 32 * j;
            float2 f0 = __half22float2(acc[i][j][0]);
            float2 f1 = __half22float2(acc[i][j][1]);
            float tot = (f0.x + f0.y) + (f1.x + f1.y);
            oblk[(size_t)(n * NROW + m) * 3 + 2] = fmaf(2.0f, tot, -(sxn + sys[m]));
        }
    }

    // cos / l2 from MMA fragments
    {
        const int rn_[2] = {n0 + g_, n0 + g_ + 8};
        const int cm_[2] = {m0 + 2 * tg, m0 + 2 * tg + 1};
        const float cv[2][2] = {{c0, c1}, {c2, c3}};
#pragma unroll
        for (int i = 0; i < 2; i++) {
            const int n = rn_[i];
            const float xn2 = nx2[n];
            const float rxn = rnx[n];
#pragma unroll
            for (int j = 0; j < 2; j++) {
                const int m = cm_[j];
                const float dotv = cv[i][j];
                float l2v = sqrtf(fmaxf(xn2 + ny2[m] - 2.0f * dotv, 0.0f));
                float cosv = dotv * rxn * rny[m];
                float* o = oblk + (size_t)(n * NROW + m) * 3;
                o[0] = cosv;
                o[1] = l2v;
            }
        }
    }
}

extern "C" void kernel_launch(void* const* d_in, const int* in_sizes, int n_in,
                              void* d_out, int out_size) {
    const float* X = (const float*)d_in[0];
    const float* Y = (const float*)d_in[1];
    float* out = (float*)d_out;

    cudaFuncSetAttribute(vcmp_kernel, cudaFuncAttributeMaxDynamicSharedMemorySize,
                         SMEM_BYTES);
    vcmp_kernel<<<NBLK, NTHR, SMEM_BYTES>>>(X, Y, out);
}

// round 16
// speedup vs baseline: 1.2010x; 1.2010x over previous
#include <cuda_runtime.h>
#include <cuda_fp16.h>
#include <cstdint>

// Problem constants: S=16, P=8, N=64, D=128
#define NBLK   128
#define NROW   64
#define DIMD   128
#define QH     68      // half2 row stride (68 mod 32 == 4 -> conflict-free LDS.128)
#define NTHR   1024

// smem: qx[64][68](u32/half2), qy[64][68], nx2/rnx/ny2/rny/sxs/sys[64]
#define SMEM_BYTES (2 * NROW * QH * 4 + 6 * NROW * 4)

__device__ __forceinline__ __half2 asH2(uint32_t u) {
    __half2 h;
    *(uint32_t*)&h = u;
    return h;
}

__global__ void __launch_bounds__(NTHR, 1)
vcmp_kernel(const float* __restrict__ X, const float* __restrict__ Y,
            float* __restrict__ out) {
    extern __shared__ uint32_t smem_u[];
    uint32_t* qx = smem_u;
    uint32_t* qy = qx + NROW * QH;
    float* nx2 = (float*)(qy + NROW * QH);
    float* rnx = nx2 + NROW;
    float* ny2 = rnx + NROW;
    float* rny = ny2 + NROW;
    float* sxs = rny + NROW;
    float* sys = sxs + NROW;

    const int blk = blockIdx.x;
    const int t   = threadIdx.x;
    const int wid = t >> 5;
    const int lid = t & 31;

    // ---- Fused load + fp16 convert + per-row reductions (all 32 warps) ----
    const float4* xg = (const float4*)(X + (size_t)blk * NROW * DIMD);
    const float4* yg = (const float4*)(Y + (size_t)blk * NROW * DIMD);
#pragma unroll
    for (int k = 0; k < 2; k++) {
        const int g    = k * NTHR + t;
        const int row  = k * 32 + wid;
        const int word = (g & 31) * 2;
        float4 xv = xg[g];
        float4 yv = yg[g];

        __half2 hx0 = __float22half2_rn(make_float2(xv.x, xv.y));
        __half2 hx1 = __float22half2_rn(make_float2(xv.z, xv.w));
        __half2 hy0 = __float22half2_rn(make_float2(yv.x, yv.y));
        __half2 hy1 = __float22half2_rn(make_float2(yv.z, yv.w));
        *(uint2*)(qx + row * QH + word) = make_uint2(*(uint32_t*)&hx0, *(uint32_t*)&hx1);
        *(uint2*)(qy + row * QH + word) = make_uint2(*(uint32_t*)&hy0, *(uint32_t*)&hy1);

        float2 fx0 = __half22float2(hx0), fx1 = __half22float2(hx1);
        float2 fy0 = __half22float2(hy0), fy1 = __half22float2(hy1);
        float ssx = fx0.x*fx0.x + fx0.y*fx0.y + fx1.x*fx1.x + fx1.y*fx1.y;
        float sx_ = fx0.x + fx0.y + fx1.x + fx1.y;
        float ssy = fy0.x*fy0.x + fy0.y*fy0.y + fy1.x*fy1.x + fy1.y*fy1.y;
        float sy_ = fy0.x + fy0.y + fy1.x + fy1.y;
#pragma unroll
        for (int off = 16; off > 0; off >>= 1) {
            ssx += __shfl_xor_sync(0xffffffffu, ssx, off);
            sx_ += __shfl_xor_sync(0xffffffffu, sx_, off);
            ssy += __shfl_xor_sync(0xffffffffu, ssy, off);
            sy_ += __shfl_xor_sync(0xffffffffu, sy_, off);
        }
        if (lid == 0) {
            nx2[row] = ssx;
            rnx[row] = 1.0f / fmaxf(sqrtf(ssx), 1e-12f);
            sxs[row] = sx_;
            ny2[row] = ssy;
            rny[row] = 1.0f / fmaxf(sqrtf(ssy), 1e-12f);
            sys[row] = sy_;
        }
    }
    __syncthreads();

    float* oblk = out + (size_t)blk * NROW * NROW * 3;

    if (wid < 16) {
        // ================= MMA warps: Gram 16x16 tile + cos/l2 epilogue ========
        // warp M: n0 = (M>>2)*16, m0 = (M&3)*16; two m16n8k16 tiles share A frags
        const int g_ = lid >> 2;
        const int tg = lid & 3;
        const int n0 = (wid >> 2) * 16;
        const int m0 = (wid & 3) * 16;

        float c[2][4] = {{0.f,0.f,0.f,0.f},{0.f,0.f,0.f,0.f}};
        {
            const uint32_t* pa  = qx + (n0 + g_) * QH + tg;
            const uint32_t* pb0 = qy + (m0 + g_) * QH + tg;
            const uint32_t* pb1 = qy + (m0 + 8 + g_) * QH + tg;
#pragma unroll
            for (int kk = 0; kk < 8; kk++) {
                const int w = kk * 8;
                uint32_t a0 = pa[w];
                uint32_t a1 = pa[8 * QH + w];
                uint32_t a2 = pa[w + 4];
                uint32_t a3 = pa[8 * QH + w + 4];
                uint32_t b0 = pb0[w];
                uint32_t b1 = pb0[w + 4];
                uint32_t b2 = pb1[w];
                uint32_t b3 = pb1[w + 4];
                asm volatile(
                    "mma.sync.aligned.m16n8k16.row.col.f32.f16.f16.f32 "
                    "{%0,%1,%2,%3}, {%4,%5,%6,%7}, {%8,%9}, {%0,%1,%2,%3};"
                    : "+f"(c[0][0]), "+f"(c[0][1]), "+f"(c[0][2]), "+f"(c[0][3])
                    : "r"(a0), "r"(a1), "r"(a2), "r"(a3), "r"(b0), "r"(b1));
                asm volatile(
                    "mma.sync.aligned.m16n8k16.row.col.f32.f16.f16.f32 "
                    "{%0,%1,%2,%3}, {%4,%5,%6,%7}, {%8,%9}, {%0,%1,%2,%3};"
                    : "+f"(c[1][0]), "+f"(c[1][1]), "+f"(c[1][2]), "+f"(c[1][3])
                    : "r"(a0), "r"(a1), "r"(a2), "r"(a3), "r"(b2), "r"(b3));
            }
        }

        // epilogue: per tile tj, rows n0+g_, n0+g_+8; cols m0+tj*8+2*tg (+1)
#pragma unroll
        for (int tj = 0; tj < 2; tj++) {
            const int rn_[2] = {n0 + g_, n0 + g_ + 8};
            const int cm_[2] = {m0 + tj * 8 + 2 * tg, m0 + tj * 8 + 2 * tg + 1};
#pragma unroll
            for (int i = 0; i < 2; i++) {
                const int n = rn_[i];
                const float xn2 = nx2[n];
                const float rxn = rnx[n];
#pragma unroll
                for (int j = 0; j < 2; j++) {
                    const int m = cm_[j];
                    const float dotv = c[tj][i * 2 + j];
                    float l2v = sqrtf(fmaxf(xn2 + ny2[m] - 2.0f * dotv, 0.0f));
                    float cosv = dotv * rxn * rny[m];
                    float* o = oblk + (size_t)(n * NROW + m) * 3;
                    o[0] = cosv;
                    o[1] = l2v;
                }
            }
        }
    } else {
        // ================= L1 warps: fp16 Sum(max), 4x2 pair tile ==============
        // warp L = wid-16: rows n = L*4+i (i<4), cols m = lid + 32*j (j<2)
        const int L = wid - 16;
        const uint32_t* xq = qx + (L * 4) * QH;
        const uint32_t* yq0 = qy + lid * QH;
        const uint32_t* yq1 = yq0 + 32 * QH;

        __half2 acc[4][2][2];
#pragma unroll
        for (int i = 0; i < 4; i++)
#pragma unroll
            for (int j = 0; j < 2; j++) {
                acc[i][j][0] = __float2half2_rn(0.f);
                acc[i][j][1] = __float2half2_rn(0.f);
            }

#pragma unroll
        for (int d2 = 0; d2 < 64; d2 += 4) {   // 16 iterations, 4 half2 per row
            uint4 xr[4];
#pragma unroll
            for (int i = 0; i < 4; i++)
                xr[i] = *(const uint4*)(xq + i * QH + d2);   // broadcast
            uint4 y0 = *(const uint4*)(yq0 + d2);            // conflict-free
            uint4 y1 = *(const uint4*)(yq1 + d2);
#pragma unroll
            for (int i = 0; i < 4; i++) {
#pragma unroll
                for (int j = 0; j < 2; j++) {
                    const uint4 yy = (j == 0) ? y0 : y1;
                    __half2 m0 = __hmax2(asH2(xr[i].x), asH2(yy.x));
                    __half2 m1 = __hmax2(asH2(xr[i].y), asH2(yy.y));
                    __half2 m2 = __hmax2(asH2(xr[i].z), asH2(yy.z));
                    __half2 m3 = __hmax2(asH2(xr[i].w), asH2(yy.w));
                    acc[i][j][0] = __hadd2(acc[i][j][0], __hadd2(m0, m1));
                    acc[i][j][1] = __hadd2(acc[i][j][1], __hadd2(m2, m3));
                }
            }
        }

        // L1 = 2*Sum(max) - Sx - Sy
#pragma unroll
        for (int i = 0; i < 4; i++) {
            const int n = L * 4 + i;
            const float sxn = sxs[n];
#pragma unroll
            for (int j = 0; j < 2; j++) {
                const int m = lid + 32 * j;
                float2 f0 = __half22float2(acc[i][j][0]);
                float2 f1 = __half22float2(acc[i][j][1]);
                float tot = (f0.x + f0.y) + (f1.x + f1.y);
                oblk[(size_t)(n * NROW + m) * 3 + 2] = fmaf(2.0f, tot, -(sxn + sys[m]));
            }
        }
    }
}

extern "C" void kernel_launch(void* const* d_in, const int* in_sizes, int n_in,
                              void* d_out, int out_size) {
    const float* X = (const float*)d_in[0];
    const float* Y = (const float*)d_in[1];
    float* out = (float*)d_out;

    cudaFuncSetAttribute(vcmp_kernel, cudaFuncAttributeMaxDynamicSharedMemorySize,
                         SMEM_BYTES);
    vcmp_kernel<<<NBLK, NTHR, SMEM_BYTES>>>(X, Y, out);
}